// round 15
// baseline (speedup 1.0000x reference)
#include <cuda_runtime.h>
#include <cuda_fp16.h>
#include <math.h>
#include <stdint.h>

// ---------------- problem constants (fixed shapes) ----------------
#define Bsz   4
#define Ntok  16384
#define Dm    256
#define LDm   64
#define Hm    128
#define Wm    128
#define HWm   (Hm*Wm)
#define Hsrc  512
#define Wsrc  512
#define CATD  320
#define HIDD  1024
#define Mrows (Bsz*Ntok)
#define ACCW  260        // 256 channels + mask + pad to 16B-aligned rows

// ---------------- scratch (static device globals; no allocs) ------
// g_acc invariant: zero at kernel_launch entry (zero-inited at module load,
// re-zeroed after each recon+gather, overlapped with downstream work).
__device__ __align__(16) float  g_loc_extra[Bsz*Ntok*2];
__device__ __align__(16) float  g_acc [(size_t)Bsz*HWm*ACCW];
__device__ __align__(16) __half g_fmap[(size_t)Bsz*HWm*256];
__device__ __align__(16) __half g_cat[(size_t)Mrows*CATD];
__device__ __align__(16) __half g_hid[(size_t)Mrows*HIDD];
__device__ __align__(16) __half g_w1[(size_t)HIDD*CATD];     // fc1_w^T fp16 [N][K]
__device__ __align__(16) __half g_w2[(size_t)Dm*HIDD];       // fc2_w^T fp16 [N][K]

// ================= PTX helpers (base sm_80/sm_90 features only) =====
__device__ __forceinline__ uint32_t smem_u32(const void* p) {
    uint32_t a;
    asm("{ .reg .u64 t; cvta.to.shared.u64 t, %1; cvt.u32.u64 %0, t; }" : "=r"(a) : "l"(p));
    return a;
}
#define CP16(smem, gptr) \
    asm volatile("cp.async.cg.shared.global [%0], [%1], 16;" :: "r"(smem), "l"(gptr) : "memory")
#define CP_COMMIT() asm volatile("cp.async.commit_group;" ::: "memory")
#define CP_WAIT1()  asm volatile("cp.async.wait_group 1;" ::: "memory")

__device__ __forceinline__ void ldsm4(uint32_t* r, uint32_t addr) {
    asm volatile("ldmatrix.sync.aligned.m8n8.x4.shared.b16 {%0,%1,%2,%3}, [%4];"
        : "=r"(r[0]), "=r"(r[1]), "=r"(r[2]), "=r"(r[3]) : "r"(addr));
}
__device__ __forceinline__ void mma16816(float* d, const uint32_t* a, const uint32_t* b) {
    asm volatile("mma.sync.aligned.m16n8k16.row.col.f32.f16.f16.f32 "
        "{%0,%1,%2,%3}, {%4,%5,%6,%7}, {%8,%9}, {%0,%1,%2,%3};"
        : "+f"(d[0]), "+f"(d[1]), "+f"(d[2]), "+f"(d[3])
        : "r"(a[0]), "r"(a[1]), "r"(a[2]), "r"(a[3]), "r"(b[0]), "r"(b[1]));
}
__device__ __forceinline__ void red_add_v4(float* p, float4 v) {
    asm volatile("red.global.add.v4.f32 [%0], {%1,%2,%3,%4};"
        :: "l"(p), "f"(v.x), "f"(v.y), "f"(v.z), "f"(v.w) : "memory");
}

// ---------------- K0: zero the scatter accumulator (for NEXT call)
__global__ void k_zero_acc() {
    size_t n4 = (size_t)Bsz*HWm*ACCW/4;
    size_t i = (size_t)blockIdx.x*blockDim.x + threadIdx.x;
    if (i < n4) ((float4*)g_acc)[i] = make_float4(0.f,0.f,0.f,0.f);
}

// ---------------- K1: LN1 + delta + loc_extra + loc + x-copy ------
__global__ void k_delta(const float* __restrict__ x, const float* __restrict__ loc,
                        const float* __restrict__ wd, const float* __restrict__ bd,
                        const float* __restrict__ n1g, const float* __restrict__ n1b,
                        float* __restrict__ out, float* __restrict__ out_loc_base)
{
    int w = (blockIdx.x*blockDim.x + threadIdx.x) >> 5;
    int lane = threadIdx.x & 31;
    if (w >= Bsz*Ntok) return;
    int b = w >> 14, n = w & 16383;
    const float* xr = x + (size_t)w*Dm;
    float* orow = out + ((size_t)b*2*Ntok + n)*Dm;
    float v[8], s = 0.f, sq = 0.f;
#pragma unroll
    for (int k = 0; k < 8; k++) {
        v[k] = xr[lane + 32*k];
        orow[lane + 32*k] = v[k];          // fused x -> out copy
        s += v[k]; sq += v[k]*v[k];
    }
#pragma unroll
    for (int o = 16; o > 0; o >>= 1) { s += __shfl_xor_sync(0xffffffffu, s, o); sq += __shfl_xor_sync(0xffffffffu, sq, o); }
    float m   = s  * (1.f/256.f);
    float var = sq * (1.f/256.f) - m*m;
    float r   = rsqrtf(var + 1e-5f);
    float d0 = 0.f, d1 = 0.f;
#pragma unroll
    for (int k = 0; k < 8; k++) {
        int c = lane + 32*k;
        float y = (v[k]-m)*r*n1g[c] + n1b[c];
        d0 += y * wd[2*c];
        d1 += y * wd[2*c+1];
    }
#pragma unroll
    for (int o = 16; o > 0; o >>= 1) { d0 += __shfl_xor_sync(0xffffffffu, d0, o); d1 += __shfl_xor_sync(0xffffffffu, d1, o); }
    if (lane == 0) {
        float l0 = loc[2*w], l1 = loc[2*w+1];
        float e0 = fminf(fmaxf(l0 + (d0 + bd[0])*0.01f, 0.f), 1.f);
        float e1 = fminf(fmaxf(l1 + (d1 + bd[1])*0.01f, 0.f), 1.f);
        g_loc_extra[2*w]   = e0;
        g_loc_extra[2*w+1] = e1;
        float* o1 = out_loc_base + ((size_t)b*2*Ntok + n)*2;
        o1[0] = l0; o1[1] = l1;
        float* o2 = out_loc_base + ((size_t)b*2*Ntok + Ntok + n)*2;
        o2[0] = e0; o2[1] = e1;
    }
}

// ---------------- K3: token2map scatter-add (v4 reductions) -------
__global__ void k_scatter(const float* __restrict__ x, const float* __restrict__ loc)
{
    int w = (blockIdx.x*blockDim.x + threadIdx.x) >> 5;
    int lane = threadIdx.x & 31;
    if (w >= Bsz*Ntok) return;
    int b = w >> 14;
    float lx = fminf(fmaxf(loc[2*w],   0.f), 1.f) * (float)(Wm-1);
    float ly = fminf(fmaxf(loc[2*w+1], 0.f), 1.f) * (float)(Hm-1);
    int xi = (int)rintf(lx);
    int yi = (int)rintf(ly);
    size_t base = ((size_t)b*HWm + yi*Wm + xi) * ACCW;
    const float4* xr4 = (const float4*)(x + (size_t)w*Dm);
#pragma unroll
    for (int p = lane; p < 64; p += 32)
        red_add_v4(&g_acc[base + 4*p], xr4[p]);
    if (lane == 0)
        atomicAdd(&g_acc[base + 256], 1.f);
}

// ---------------- K5: fused normalize + gaussian 3x3 + reconstruct
__global__ void k_recon()
{
    int tile = blockIdx.x;                 // 0 .. B*HW/32-1 (2048)
    int b    = tile >> 9;
    int rem  = tile & 511;
    int y0   = (rem >> 4) << 2;
    int x0   = (rem & 15) << 3;
    int c    = threadIdx.x;                // 0..255 = channel

    __shared__ float s_inv[6][10];
    __shared__ float s_msk[6][10];

    if (c < 60) {
        int r = c / 10, cc = c % 10;
        int ny = y0 - 1 + r, nx = x0 - 1 + cc;
        bool valid = (ny >= 0 && ny < Hm && nx >= 0 && nx < Wm);
        float cnt = valid ? g_acc[((size_t)b*HWm + ny*Wm + nx)*ACCW + 256] : 0.f;
        float msk = (valid && cnt > 0.f) ? 1.f : 0.f;
        s_msk[r][cc] = msk;
        s_inv[r][cc] = valid ? (msk / (cnt + 1e-6f)) : 0.f;
    }
    __syncthreads();

    float e1 = expf(-0.125f), e2 = expf(-0.25f);
    float wsum = 1.f + 4.f*e1 + 4.f*e2;
    float w0 = 1.f/wsum, w1 = e1/wsum, w2 = e2/wsum;

    float vals[3][10];
#define LOAD_ROW(r, slot) do { \
    int _ny = y0 - 1 + (r); \
    bool _rok = (_ny >= 0 && _ny < Hm); \
    _Pragma("unroll") \
    for (int _cc = 0; _cc < 10; _cc++) { \
        int _nx = x0 - 1 + _cc; \
        bool _ok = _rok && (_nx >= 0 && _nx < Wm); \
        float _v = _ok ? g_acc[((size_t)b*HWm + _ny*Wm + _nx)*ACCW + c] : 0.f; \
        vals[slot][_cc] = _v * s_inv[r][_cc]; \
    } \
} while (0)

    LOAD_ROW(0, 0);
    LOAD_ROW(1, 1);

#pragma unroll
    for (int yi = 0; yi < 4; yi++) {
        LOAD_ROW(yi + 2, (yi + 2) % 3);
        float* vm = vals[yi % 3];
        float* v0 = vals[(yi + 1) % 3];
        float* vp = vals[(yi + 2) % 3];
        const float* mm = s_msk[yi];
        const float* m0 = s_msk[yi + 1];
        const float* mp = s_msk[yi + 2];
#pragma unroll
        for (int i = 0; i < 8; i++) {
            float feature = v0[i + 1];
            float mask_c  = m0[i + 1];
            float filt  = w0*v0[i+1]
                        + w1*(v0[i] + v0[i+2] + vm[i+1] + vp[i+1])
                        + w2*(vm[i] + vm[i+2] + vp[i] + vp[i+2]);
            float filtm = w0*m0[i+1]
                        + w1*(m0[i] + m0[i+2] + mm[i+1] + mp[i+1])
                        + w2*(mm[i] + mm[i+2] + mp[i] + mp[i+2]);
            float f_i = filt / (filtm + 1e-6f);
            f_i = (filtm > 0.f) ? f_i : 0.f;
            float outv = feature + (1.f - mask_c)*f_i;
            g_fmap[((size_t)b*HWm + (y0 + yi)*Wm + x0 + i)*256 + c] = __float2half_rn(outv);
        }
    }
#undef LOAD_ROW
}

// ---------------- K6: patch sample + conv + LN2 (8 tokens/block) --
__device__ __forceinline__ float srctap(const float* sp, int xi, int yi, float w)
{
    if (xi < 0 || xi >= Wsrc || yi < 0 || yi >= Hsrc) return 0.f;
    return w * sp[yi*Wsrc + xi];
}

__global__ __launch_bounds__(512) void k_patch(const float* __restrict__ src,
                        const float* __restrict__ cw,
                        const float* __restrict__ cb,  const float* __restrict__ n2g,
                        const float* __restrict__ n2b)
{
    __shared__ float s_cw[64*49];
    __shared__ float s_patch[8][48];
    __shared__ float s_red[8][4];

    int tid = threadIdx.x;
    for (int i = tid; i < 64*48; i += 512)
        s_cw[(i/48)*49 + (i%48)] = cw[i];

    int sub = tid >> 6;
    int t   = tid & 63;
    int tok = blockIdx.x*8 + sub;
    int b   = tok >> 14;

    float lx = g_loc_extra[2*tok], ly = g_loc_extra[2*tok+1];
    if (t < 48) {
        int cch = t >> 4, r = (t >> 2) & 3, col = t & 3;
        float gx = (lx + ((float)col - 1.5f)*(1.f/511.f)) * 512.f - 0.5f;
        float gy = (ly + ((float)r   - 1.5f)*(1.f/511.f)) * 512.f - 0.5f;
        float x0f = floorf(gx), y0f = floorf(gy);
        float wx = gx - x0f, wy = gy - y0f;
        int x0 = (int)x0f, y0 = (int)y0f;
        const float* sp = src + ((size_t)b*3 + cch)*Hsrc*Wsrc;
        float v = srctap(sp, x0,   y0,   (1.f-wx)*(1.f-wy))
                + srctap(sp, x0+1, y0,   wx*(1.f-wy))
                + srctap(sp, x0,   y0+1, (1.f-wx)*wy)
                + srctap(sp, x0+1, y0+1, wx*wy);
        s_patch[sub][t] = v;
    }
    __syncthreads();

    float acc = cb[t];
#pragma unroll
    for (int k = 0; k < 48; k++) acc += s_patch[sub][k] * s_cw[t*49 + k];

    float s = acc, sq = acc*acc;
#pragma unroll
    for (int o = 16; o > 0; o >>= 1) { s += __shfl_xor_sync(0xffffffffu, s, o); sq += __shfl_xor_sync(0xffffffffu, sq, o); }
    int wh = t >> 5;
    if ((t & 31) == 0) { s_red[sub][wh] = s; s_red[sub][2 + wh] = sq; }
    __syncthreads();
    s  = s_red[sub][0] + s_red[sub][1];
    sq = s_red[sub][2] + s_red[sub][3];
    float m   = s  * (1.f/64.f);
    float var = sq * (1.f/64.f) - m*m;
    float rr  = rsqrtf(var + 1e-5f);
    float v = (acc - m)*rr*n2g[t] + n2b[t];
    g_cat[(size_t)tok*CATD + 256 + t] = __float2half_rn(v);
}

// ---------------- K7: bilinear gather from fmap (fp16) -> cat -----
__global__ void k_gather()
{
    int tok = (blockIdx.x*blockDim.x + threadIdx.x) >> 5;
    int lane = threadIdx.x & 31;
    if (tok >= Bsz*Ntok) return;
    int b = tok >> 14;
    float gx = g_loc_extra[2*tok]   * 128.f - 0.5f;
    float gy = g_loc_extra[2*tok+1] * 128.f - 0.5f;
    float x0f = floorf(gx), y0f = floorf(gy);
    float wx = gx - x0f, wy = gy - y0f;
    int x0 = (int)x0f, y0 = (int)y0f;
    int x1 = x0 + 1,   y1 = y0 + 1;
    float vx0 = (x0 >= 0 && x0 < Wm) ? 1.f : 0.f;
    float vx1 = (x1 >= 0 && x1 < Wm) ? 1.f : 0.f;
    float vy0 = (y0 >= 0 && y0 < Hm) ? 1.f : 0.f;
    float vy1 = (y1 >= 0 && y1 < Hm) ? 1.f : 0.f;
    float w00 = (1.f-wx)*(1.f-wy)*vx0*vy0;
    float w10 = wx*(1.f-wy)*vx1*vy0;
    float w01 = (1.f-wx)*wy*vx0*vy1;
    float w11 = wx*wy*vx1*vy1;
    int cx0 = min(max(x0,0),Wm-1), cx1 = min(max(x1,0),Wm-1);
    int cy0 = min(max(y0,0),Hm-1), cy1 = min(max(y1,0),Hm-1);
    const __half* base = g_fmap + (size_t)b*HWm*256;
    const __half2* p00 = (const __half2*)(base + (size_t)(cy0*Wm + cx0)*256);
    const __half2* p10 = (const __half2*)(base + (size_t)(cy0*Wm + cx1)*256);
    const __half2* p01 = (const __half2*)(base + (size_t)(cy1*Wm + cx0)*256);
    const __half2* p11 = (const __half2*)(base + (size_t)(cy1*Wm + cx1)*256);
    __half2* outp = (__half2*)(g_cat + (size_t)tok*CATD);
#pragma unroll
    for (int k = 0; k < 4; k++) {
        int p = lane + 32*k;
        float2 a = __half22float2(p00[p]);
        float2 d = __half22float2(p10[p]);
        float2 e = __half22float2(p01[p]);
        float2 f = __half22float2(p11[p]);
        float r0 = w00*a.x + w10*d.x + w01*e.x + w11*f.x;
        float r1 = w00*a.y + w10*d.y + w01*e.y + w11*f.y;
        outp[p] = __floats2half2_rn(r0, r1);
    }
}

// ---------------- weight transpose + fp16: [K][N] -> [N][K] -------
__global__ void k_wsplit(const float* __restrict__ in, int K, int N, int which)
{
    __half* oh = which ? g_w2 : g_w1;
    __shared__ float t[32][33];
    int k0 = blockIdx.y*32, n0 = blockIdx.x*32;
    int x = threadIdx.x, y = threadIdx.y;
#pragma unroll
    for (int i = 0; i < 32; i += 8)
        t[y+i][x] = in[(size_t)(k0+y+i)*N + n0 + x];
    __syncthreads();
#pragma unroll
    for (int i = 0; i < 32; i += 8)
        oh[(size_t)(n0+y+i)*K + k0 + x] = __float2half_rn(t[x][y+i]);
}

// ---------------- HMMA fp16 GEMM (128x128 CTA, K-chunk 64) --------
#define STG   36864
#define NSTG  3
#define GEMM_SMEM (NSTG*STG)

__global__ __launch_bounds__(256, 2) void mma_gemm(const float* __restrict__ bias,
                                                   float* __restrict__ outp,
                                                   int K, int Nn, int epi, int bm0)
{
    extern __shared__ char smem[];
    uint32_t sb = smem_u32(smem);

    const __half *Ah, *Bw;
    if (epi == 0) { Ah = g_cat; Bw = g_w1; }
    else          { Ah = g_hid; Bw = g_w2; }

    int tid = threadIdx.x, lane = tid & 31, wid = tid >> 5;
    int warpM = wid & 1, warpN = wid >> 1;
    int bm = bm0 + blockIdx.y*128, bn = blockIdx.x*128;
    int nch = K >> 6;

    const __half* Abase = Ah + (size_t)bm*K;
    const __half* Bbase = Bw + (size_t)bn*K;

    float acc[4][4][4];
#pragma unroll
    for (int a = 0; a < 4; a++)
#pragma unroll
        for (int b = 0; b < 4; b++)
#pragma unroll
            for (int c = 0; c < 4; c++) acc[a][b][c] = 0.f;

#define LOAD_CHUNK(i) do { \
    int _k0 = (i) << 6; \
    uint32_t _st = sb + ((i) % NSTG) * STG; \
    _Pragma("unroll") \
    for (int _j = 0; _j < 4; _j++) { \
        int _u = tid + _j*256; \
        int _r = _u >> 3, _kb = _u & 7; \
        size_t _go = (size_t)_r*K + _k0 + _kb*8; \
        uint32_t _do_ = (uint32_t)(_r*144 + _kb*16); \
        CP16(_st + _do_,          Abase + _go); \
        CP16(_st + 18432 + _do_,  Bbase + _go); \
    } \
} while (0)

    LOAD_CHUNK(0); CP_COMMIT();
    if (nch > 1) LOAD_CHUNK(1);
    CP_COMMIT();

    int arow = warpM*64 + (lane & 7) + ((lane >> 3) & 1)*8;
    uint32_t akb = ((lane >> 4) & 1)*16;
    int brow = warpN*32 + ((lane >> 4) & 1)*8 + (lane & 7);
    uint32_t bkb = ((lane >> 3) & 1)*16;

    uint32_t a4[2][4][4], bfr[2][2][4];    // ks-parity double buffers

#define LD_FRAGS(st, kB, pb) do { \
    _Pragma("unroll") \
    for (int _mf = 0; _mf < 4; _mf++) \
        ldsm4(a4[pb][_mf], (st) + (uint32_t)(arow + _mf*16)*144 + akb + (kB)); \
    _Pragma("unroll") \
    for (int _np = 0; _np < 2; _np++) \
        ldsm4(bfr[pb][_np], (st) + 18432 + (uint32_t)(brow + _np*16)*144 + bkb + (kB)); \
} while (0)

    for (int i = 0; i < nch; i++) {
        CP_WAIT1();
        __syncthreads();
        if (i + 2 < nch) LOAD_CHUNK(i + 2);
        CP_COMMIT();

        uint32_t st = sb + (i % NSTG)*STG;
        LD_FRAGS(st, 0u, 0);
#pragma unroll
        for (int ks = 0; ks < 4; ks++) {
            int cur = ks & 1;
            if (ks < 3) LD_FRAGS(st, (uint32_t)(ks+1)*32, cur ^ 1);
#pragma unroll
            for (int mf = 0; mf < 4; mf++)
#pragma unroll
                for (int nf = 0; nf < 4; nf++) {
                    const uint32_t* bp = &bfr[cur][nf >> 1][(nf & 1)*2];
                    mma16816(acc[mf][nf], a4[cur][mf], bp);
                }
        }
    }
#undef LD_FRAGS

    // ---- epilogue (direct stores) ----
    int r0 = bm + warpM*64 + (lane >> 2);
    int cbase = bn + warpN*32 + (lane & 3)*2;
#pragma unroll
    for (int mf = 0; mf < 4; mf++) {
        int row0 = r0 + mf*16;
        int row1 = row0 + 8;
#pragma unroll
        for (int nf = 0; nf < 4; nf++) {
            int col = cbase + nf*8;
            float b0 = bias[col], b1 = bias[col + 1];
            float v00 = acc[mf][nf][0] + b0;
            float v01 = acc[mf][nf][1] + b1;
            float v10 = acc[mf][nf][2] + b0;
            float v11 = acc[mf][nf][3] + b1;
            if (epi == 0) {
                v00 = 0.5f*v00*(1.f + erff(v00*0.70710678118654752f));
                v01 = 0.5f*v01*(1.f + erff(v01*0.70710678118654752f));
                v10 = 0.5f*v10*(1.f + erff(v10*0.70710678118654752f));
                v11 = 0.5f*v11*(1.f + erff(v11*0.70710678118654752f));
                *(__half2*)(g_hid + (size_t)row0*HIDD + col) =
                    __half2(__float2half_rn(v00), __float2half_rn(v01));
                *(__half2*)(g_hid + (size_t)row1*HIDD + col) =
                    __half2(__float2half_rn(v10), __float2half_rn(v11));
            } else {
                int bb0 = row0 >> 14, n0 = row0 & 16383;
                int bb1 = row1 >> 14, n1 = row1 & 16383;
                size_t ob0 = (((size_t)bb0*2*Ntok) + Ntok + n0)*256;
                size_t ob1 = (((size_t)bb1*2*Ntok) + Ntok + n1)*256;
                *(float2*)(outp + ob0 + col) = make_float2(v00, v01);
                *(float2*)(outp + ob1 + col) = make_float2(v10, v11);
            }
        }
    }
}

// ---------------- launch (forked-stream graph, fully joined) -------
static cudaStream_t g_s1 = nullptr, g_s2 = nullptr;
static cudaEvent_t  g_e0 = nullptr, g_e1 = nullptr, g_e2 = nullptr,
                    g_e3 = nullptr, g_e4 = nullptr, g_e5 = nullptr, g_e6 = nullptr;

extern "C" void kernel_launch(void* const* d_in, const int* in_sizes, int n_in,
                              void* d_out, int out_size)
{
    (void)in_sizes; (void)n_in; (void)out_size;
    const float* x      = (const float*)d_in[0];
    const float* loc    = (const float*)d_in[1];
    const float* src    = (const float*)d_in[2];
    const float* w_delta = (const float*)d_in[7];
    const float* b_delta = (const float*)d_in[8];
    const float* n1g    = (const float*)d_in[9];
    const float* n1b    = (const float*)d_in[10];
    const float* conv_w = (const float*)d_in[11];
    const float* conv_b = (const float*)d_in[12];
    const float* n2g    = (const float*)d_in[13];
    const float* n2b    = (const float*)d_in[14];
    const float* fc1w   = (const float*)d_in[15];
    const float* fc1b   = (const float*)d_in[16];
    const float* fc2w   = (const float*)d_in[17];
    const float* fc2b   = (const float*)d_in[18];
    float* out = (float*)d_out;
    float* out_loc = out + (size_t)Bsz*2*Ntok*Dm;

    cudaFuncSetAttribute(mma_gemm, cudaFuncAttributeMaxDynamicSharedMemorySize, GEMM_SMEM);

    if (!g_s1) {
        cudaStreamCreateWithFlags(&g_s1, cudaStreamNonBlocking);
        cudaStreamCreateWithFlags(&g_s2, cudaStreamNonBlocking);
        cudaEventCreateWithFlags(&g_e0, cudaEventDisableTiming);
        cudaEventCreateWithFlags(&g_e1, cudaEventDisableTiming);
        cudaEventCreateWithFlags(&g_e2, cudaEventDisableTiming);
        cudaEventCreateWithFlags(&g_e3, cudaEventDisableTiming);
        cudaEventCreateWithFlags(&g_e4, cudaEventDisableTiming);
        cudaEventCreateWithFlags(&g_e5, cudaEventDisableTiming);
        cudaEventCreateWithFlags(&g_e6, cudaEventDisableTiming);
    }

    // fork
    cudaEventRecord(g_e0, 0);
    cudaStreamWaitEvent(g_s1, g_e0, 0);
    cudaStreamWaitEvent(g_s2, g_e0, 0);

    // branch s2: weight transpose + fp16 (needed by GEMMs only)
    k_wsplit<<<dim3(HIDD/32, CATD/32), dim3(32,8), 0, g_s2>>>(fc1w, CATD, HIDD, 0);
    k_wsplit<<<dim3(Dm/32,  HIDD/32), dim3(32,8), 0, g_s2>>>(fc2w, HIDD, Dm, 1);
    cudaEventRecord(g_e2, g_s2);

    // branch s1: scatter (g_acc pre-zeroed by PREVIOUS call / module init)
    k_scatter<<<Bsz*Ntok/8, 256, 0, g_s1>>>(x, loc);

    // main stream: delta (produces loc_extra), record for s1's gather
    k_delta<<<Bsz*Ntok/8, 256>>>(x, loc, w_delta, b_delta, n1g, n1b, out, out_loc);
    cudaEventRecord(g_e3, 0);

    // branch s1 continued: recon -> gather, then deferred re-zero (joined via e5)
    k_recon<<<Bsz*HWm/32, 256, 0, g_s1>>>();
    cudaStreamWaitEvent(g_s1, g_e3, 0);
    k_gather<<<Bsz*Ntok/8, 256, 0, g_s1>>>();
    cudaEventRecord(g_e1, g_s1);
    {
        size_t n4 = (size_t)Bsz*HWm*ACCW/4;
        k_zero_acc<<<(unsigned)((n4 + 255)/256), 256, 0, g_s1>>>();   // next call
    }
    cudaEventRecord(g_e5, g_s1);

    // main stream: patch (concurrent with recon/gather), then join
    k_patch<<<Bsz*Ntok/8, 512>>>(src, conv_w, conv_b, n2g, n2b);
    cudaStreamWaitEvent(0, g_e1, 0);       // cat fully ready
    cudaStreamWaitEvent(0, g_e2, 0);       // weights ready

    // MLP, M-half pipelined: GEMM2(h0) on s2 overlaps GEMM1(h1) on main
    const int MH = Mrows/2;                // 32768
    mma_gemm<<<dim3(HIDD/128, MH/128), 256, GEMM_SMEM>>>(fc1b, nullptr, CATD, HIDD, 0, 0);
    cudaEventRecord(g_e4, 0);
    mma_gemm<<<dim3(HIDD/128, MH/128), 256, GEMM_SMEM>>>(fc1b, nullptr, CATD, HIDD, 0, MH);

    cudaStreamWaitEvent(g_s2, g_e4, 0);    // hid rows [0,MH) ready
    mma_gemm<<<dim3(Dm/128, MH/128), 256, GEMM_SMEM, g_s2>>>(fc2b, out, HIDD, Dm, 1, 0);
    cudaEventRecord(g_e6, g_s2);

    mma_gemm<<<dim3(Dm/128, MH/128), 256, GEMM_SMEM>>>(fc2b, out, HIDD, Dm, 1, MH);

    // join all side streams into the capture-origin stream
    cudaStreamWaitEvent(0, g_e5, 0);       // s1 tail (deferred zero)
    cudaStreamWaitEvent(0, g_e6, 0);       // s2 tail (GEMM2 h0)
}

// round 16
// speedup vs baseline: 1.0129x; 1.0129x over previous
#include <cuda_runtime.h>
#include <cuda_fp16.h>
#include <math.h>
#include <stdint.h>

// ---------------- problem constants (fixed shapes) ----------------
#define Bsz   4
#define Ntok  16384
#define Dm    256
#define LDm   64
#define Hm    128
#define Wm    128
#define HWm   (Hm*Wm)
#define Hsrc  512
#define Wsrc  512
#define CATD  320
#define HIDD  1024
#define Mrows (Bsz*Ntok)
#define ACCW  260        // 256 channels + mask + pad to 16B-aligned rows

// ---------------- scratch (static device globals; no allocs) ------
// g_acc invariant: zero at kernel_launch entry (zero-inited at module load,
// re-zeroed after each recon+gather, overlapped with downstream work).
__device__ __align__(16) float  g_loc_extra[Bsz*Ntok*2];
__device__ __align__(16) float  g_acc [(size_t)Bsz*HWm*ACCW];
__device__ __align__(16) __half g_fmap[(size_t)Bsz*HWm*256];
__device__ __align__(16) __half g_cat[(size_t)Mrows*CATD];
__device__ __align__(16) __half g_hid[(size_t)Mrows*HIDD];
__device__ __align__(16) __half g_w1[(size_t)HIDD*CATD];     // fc1_w^T fp16 [N][K]
__device__ __align__(16) __half g_w2[(size_t)Dm*HIDD];       // fc2_w^T fp16 [N][K]

// ================= PTX helpers (base sm_80/sm_90 features only) =====
__device__ __forceinline__ uint32_t smem_u32(const void* p) {
    uint32_t a;
    asm("{ .reg .u64 t; cvta.to.shared.u64 t, %1; cvt.u32.u64 %0, t; }" : "=r"(a) : "l"(p));
    return a;
}
#define CP16(smem, gptr) \
    asm volatile("cp.async.cg.shared.global [%0], [%1], 16;" :: "r"(smem), "l"(gptr) : "memory")
#define CP_COMMIT() asm volatile("cp.async.commit_group;" ::: "memory")
#define CP_WAIT1()  asm volatile("cp.async.wait_group 1;" ::: "memory")

__device__ __forceinline__ void ldsm4(uint32_t* r, uint32_t addr) {
    asm volatile("ldmatrix.sync.aligned.m8n8.x4.shared.b16 {%0,%1,%2,%3}, [%4];"
        : "=r"(r[0]), "=r"(r[1]), "=r"(r[2]), "=r"(r[3]) : "r"(addr));
}
__device__ __forceinline__ void mma16816(float* d, const uint32_t* a, const uint32_t* b) {
    asm volatile("mma.sync.aligned.m16n8k16.row.col.f32.f16.f16.f32 "
        "{%0,%1,%2,%3}, {%4,%5,%6,%7}, {%8,%9}, {%0,%1,%2,%3};"
        : "+f"(d[0]), "+f"(d[1]), "+f"(d[2]), "+f"(d[3])
        : "r"(a[0]), "r"(a[1]), "r"(a[2]), "r"(a[3]), "r"(b[0]), "r"(b[1]));
}
__device__ __forceinline__ void red_add_v4(float* p, float4 v) {
    asm volatile("red.global.add.v4.f32 [%0], {%1,%2,%3,%4};"
        :: "l"(p), "f"(v.x), "f"(v.y), "f"(v.z), "f"(v.w) : "memory");
}

// ---------------- K0: zero the scatter accumulator (for NEXT call)
__global__ void k_zero_acc() {
    size_t n4 = (size_t)Bsz*HWm*ACCW/4;
    size_t i = (size_t)blockIdx.x*blockDim.x + threadIdx.x;
    if (i < n4) ((float4*)g_acc)[i] = make_float4(0.f,0.f,0.f,0.f);
}

// ---------------- K1: LN1 + delta + loc_extra + loc + x-copy ------
__global__ void k_delta(const float* __restrict__ x, const float* __restrict__ loc,
                        const float* __restrict__ wd, const float* __restrict__ bd,
                        const float* __restrict__ n1g, const float* __restrict__ n1b,
                        float* __restrict__ out, float* __restrict__ out_loc_base)
{
    int w = (blockIdx.x*blockDim.x + threadIdx.x) >> 5;
    int lane = threadIdx.x & 31;
    if (w >= Bsz*Ntok) return;
    int b = w >> 14, n = w & 16383;
    const float* xr = x + (size_t)w*Dm;
    float* orow = out + ((size_t)b*2*Ntok + n)*Dm;
    float v[8], s = 0.f, sq = 0.f;
#pragma unroll
    for (int k = 0; k < 8; k++) {
        v[k] = xr[lane + 32*k];
        orow[lane + 32*k] = v[k];          // fused x -> out copy
        s += v[k]; sq += v[k]*v[k];
    }
#pragma unroll
    for (int o = 16; o > 0; o >>= 1) { s += __shfl_xor_sync(0xffffffffu, s, o); sq += __shfl_xor_sync(0xffffffffu, sq, o); }
    float m   = s  * (1.f/256.f);
    float var = sq * (1.f/256.f) - m*m;
    float r   = rsqrtf(var + 1e-5f);
    float d0 = 0.f, d1 = 0.f;
#pragma unroll
    for (int k = 0; k < 8; k++) {
        int c = lane + 32*k;
        float y = (v[k]-m)*r*n1g[c] + n1b[c];
        d0 += y * wd[2*c];
        d1 += y * wd[2*c+1];
    }
#pragma unroll
    for (int o = 16; o > 0; o >>= 1) { d0 += __shfl_xor_sync(0xffffffffu, d0, o); d1 += __shfl_xor_sync(0xffffffffu, d1, o); }
    if (lane == 0) {
        float l0 = loc[2*w], l1 = loc[2*w+1];
        float e0 = fminf(fmaxf(l0 + (d0 + bd[0])*0.01f, 0.f), 1.f);
        float e1 = fminf(fmaxf(l1 + (d1 + bd[1])*0.01f, 0.f), 1.f);
        g_loc_extra[2*w]   = e0;
        g_loc_extra[2*w+1] = e1;
        float* o1 = out_loc_base + ((size_t)b*2*Ntok + n)*2;
        o1[0] = l0; o1[1] = l1;
        float* o2 = out_loc_base + ((size_t)b*2*Ntok + Ntok + n)*2;
        o2[0] = e0; o2[1] = e1;
    }
}

// ---------------- K3: token2map scatter-add (v4 reductions) -------
__global__ void k_scatter(const float* __restrict__ x, const float* __restrict__ loc)
{
    int w = (blockIdx.x*blockDim.x + threadIdx.x) >> 5;
    int lane = threadIdx.x & 31;
    if (w >= Bsz*Ntok) return;
    int b = w >> 14;
    float lx = fminf(fmaxf(loc[2*w],   0.f), 1.f) * (float)(Wm-1);
    float ly = fminf(fmaxf(loc[2*w+1], 0.f), 1.f) * (float)(Hm-1);
    int xi = (int)rintf(lx);
    int yi = (int)rintf(ly);
    size_t base = ((size_t)b*HWm + yi*Wm + xi) * ACCW;
    const float4* xr4 = (const float4*)(x + (size_t)w*Dm);
#pragma unroll
    for (int p = lane; p < 64; p += 32)
        red_add_v4(&g_acc[base + 4*p], xr4[p]);
    if (lane == 0)
        atomicAdd(&g_acc[base + 256], 1.f);
}

// ---------------- K5: fused normalize + gaussian 3x3 + reconstruct
__global__ void k_recon()
{
    int tile = blockIdx.x;                 // 0 .. B*HW/32-1 (2048)
    int b    = tile >> 9;
    int rem  = tile & 511;
    int y0   = (rem >> 4) << 2;
    int x0   = (rem & 15) << 3;
    int c    = threadIdx.x;                // 0..255 = channel

    __shared__ float s_inv[6][10];
    __shared__ float s_msk[6][10];

    if (c < 60) {
        int r = c / 10, cc = c % 10;
        int ny = y0 - 1 + r, nx = x0 - 1 + cc;
        bool valid = (ny >= 0 && ny < Hm && nx >= 0 && nx < Wm);
        float cnt = valid ? g_acc[((size_t)b*HWm + ny*Wm + nx)*ACCW + 256] : 0.f;
        float msk = (valid && cnt > 0.f) ? 1.f : 0.f;
        s_msk[r][cc] = msk;
        s_inv[r][cc] = valid ? (msk / (cnt + 1e-6f)) : 0.f;
    }
    __syncthreads();

    float e1 = expf(-0.125f), e2 = expf(-0.25f);
    float wsum = 1.f + 4.f*e1 + 4.f*e2;
    float w0 = 1.f/wsum, w1 = e1/wsum, w2 = e2/wsum;

    float vals[3][10];
#define LOAD_ROW(r, slot) do { \
    int _ny = y0 - 1 + (r); \
    bool _rok = (_ny >= 0 && _ny < Hm); \
    _Pragma("unroll") \
    for (int _cc = 0; _cc < 10; _cc++) { \
        int _nx = x0 - 1 + _cc; \
        bool _ok = _rok && (_nx >= 0 && _nx < Wm); \
        float _v = _ok ? g_acc[((size_t)b*HWm + _ny*Wm + _nx)*ACCW + c] : 0.f; \
        vals[slot][_cc] = _v * s_inv[r][_cc]; \
    } \
} while (0)

    LOAD_ROW(0, 0);
    LOAD_ROW(1, 1);

#pragma unroll
    for (int yi = 0; yi < 4; yi++) {
        LOAD_ROW(yi + 2, (yi + 2) % 3);
        float* vm = vals[yi % 3];
        float* v0 = vals[(yi + 1) % 3];
        float* vp = vals[(yi + 2) % 3];
        const float* mm = s_msk[yi];
        const float* m0 = s_msk[yi + 1];
        const float* mp = s_msk[yi + 2];
#pragma unroll
        for (int i = 0; i < 8; i++) {
            float feature = v0[i + 1];
            float mask_c  = m0[i + 1];
            float filt  = w0*v0[i+1]
                        + w1*(v0[i] + v0[i+2] + vm[i+1] + vp[i+1])
                        + w2*(vm[i] + vm[i+2] + vp[i] + vp[i+2]);
            float filtm = w0*m0[i+1]
                        + w1*(m0[i] + m0[i+2] + mm[i+1] + mp[i+1])
                        + w2*(mm[i] + mm[i+2] + mp[i] + mp[i+2]);
            float f_i = filt / (filtm + 1e-6f);
            f_i = (filtm > 0.f) ? f_i : 0.f;
            float outv = feature + (1.f - mask_c)*f_i;
            g_fmap[((size_t)b*HWm + (y0 + yi)*Wm + x0 + i)*256 + c] = __float2half_rn(outv);
        }
    }
#undef LOAD_ROW
}

// ---------------- K6: patch sample + conv + LN2 (8 tokens/block) --
__device__ __forceinline__ float srctap(const float* sp, int xi, int yi, float w)
{
    if (xi < 0 || xi >= Wsrc || yi < 0 || yi >= Hsrc) return 0.f;
    return w * sp[yi*Wsrc + xi];
}

__global__ __launch_bounds__(512) void k_patch(const float* __restrict__ src,
                        const float* __restrict__ cw,
                        const float* __restrict__ cb,  const float* __restrict__ n2g,
                        const float* __restrict__ n2b)
{
    __shared__ float s_cw[64*49];
    __shared__ float s_patch[8][48];
    __shared__ float s_red[8][4];

    int tid = threadIdx.x;
    for (int i = tid; i < 64*48; i += 512)
        s_cw[(i/48)*49 + (i%48)] = cw[i];

    int sub = tid >> 6;
    int t   = tid & 63;
    int tok = blockIdx.x*8 + sub;
    int b   = tok >> 14;

    float lx = g_loc_extra[2*tok], ly = g_loc_extra[2*tok+1];
    if (t < 48) {
        int cch = t >> 4, r = (t >> 2) & 3, col = t & 3;
        float gx = (lx + ((float)col - 1.5f)*(1.f/511.f)) * 512.f - 0.5f;
        float gy = (ly + ((float)r   - 1.5f)*(1.f/511.f)) * 512.f - 0.5f;
        float x0f = floorf(gx), y0f = floorf(gy);
        float wx = gx - x0f, wy = gy - y0f;
        int x0 = (int)x0f, y0 = (int)y0f;
        const float* sp = src + ((size_t)b*3 + cch)*Hsrc*Wsrc;
        float v = srctap(sp, x0,   y0,   (1.f-wx)*(1.f-wy))
                + srctap(sp, x0+1, y0,   wx*(1.f-wy))
                + srctap(sp, x0,   y0+1, (1.f-wx)*wy)
                + srctap(sp, x0+1, y0+1, wx*wy);
        s_patch[sub][t] = v;
    }
    __syncthreads();

    float acc = cb[t];
#pragma unroll
    for (int k = 0; k < 48; k++) acc += s_patch[sub][k] * s_cw[t*49 + k];

    float s = acc, sq = acc*acc;
#pragma unroll
    for (int o = 16; o > 0; o >>= 1) { s += __shfl_xor_sync(0xffffffffu, s, o); sq += __shfl_xor_sync(0xffffffffu, sq, o); }
    int wh = t >> 5;
    if ((t & 31) == 0) { s_red[sub][wh] = s; s_red[sub][2 + wh] = sq; }
    __syncthreads();
    s  = s_red[sub][0] + s_red[sub][1];
    sq = s_red[sub][2] + s_red[sub][3];
    float m   = s  * (1.f/64.f);
    float var = sq * (1.f/64.f) - m*m;
    float rr  = rsqrtf(var + 1e-5f);
    float v = (acc - m)*rr*n2g[t] + n2b[t];
    g_cat[(size_t)tok*CATD + 256 + t] = __float2half_rn(v);
}

// ---------------- K7: bilinear gather from fmap (fp16) -> cat -----
__global__ void k_gather()
{
    int tok = (blockIdx.x*blockDim.x + threadIdx.x) >> 5;
    int lane = threadIdx.x & 31;
    if (tok >= Bsz*Ntok) return;
    int b = tok >> 14;
    float gx = g_loc_extra[2*tok]   * 128.f - 0.5f;
    float gy = g_loc_extra[2*tok+1] * 128.f - 0.5f;
    float x0f = floorf(gx), y0f = floorf(gy);
    float wx = gx - x0f, wy = gy - y0f;
    int x0 = (int)x0f, y0 = (int)y0f;
    int x1 = x0 + 1,   y1 = y0 + 1;
    float vx0 = (x0 >= 0 && x0 < Wm) ? 1.f : 0.f;
    float vx1 = (x1 >= 0 && x1 < Wm) ? 1.f : 0.f;
    float vy0 = (y0 >= 0 && y0 < Hm) ? 1.f : 0.f;
    float vy1 = (y1 >= 0 && y1 < Hm) ? 1.f : 0.f;
    float w00 = (1.f-wx)*(1.f-wy)*vx0*vy0;
    float w10 = wx*(1.f-wy)*vx1*vy0;
    float w01 = (1.f-wx)*wy*vx0*vy1;
    float w11 = wx*wy*vx1*vy1;
    int cx0 = min(max(x0,0),Wm-1), cx1 = min(max(x1,0),Wm-1);
    int cy0 = min(max(y0,0),Hm-1), cy1 = min(max(y1,0),Hm-1);
    const __half* base = g_fmap + (size_t)b*HWm*256;
    const __half2* p00 = (const __half2*)(base + (size_t)(cy0*Wm + cx0)*256);
    const __half2* p10 = (const __half2*)(base + (size_t)(cy0*Wm + cx1)*256);
    const __half2* p01 = (const __half2*)(base + (size_t)(cy1*Wm + cx0)*256);
    const __half2* p11 = (const __half2*)(base + (size_t)(cy1*Wm + cx1)*256);
    __half2* outp = (__half2*)(g_cat + (size_t)tok*CATD);
#pragma unroll
    for (int k = 0; k < 4; k++) {
        int p = lane + 32*k;
        float2 a = __half22float2(p00[p]);
        float2 d = __half22float2(p10[p]);
        float2 e = __half22float2(p01[p]);
        float2 f = __half22float2(p11[p]);
        float r0 = w00*a.x + w10*d.x + w01*e.x + w11*f.x;
        float r1 = w00*a.y + w10*d.y + w01*e.y + w11*f.y;
        outp[p] = __floats2half2_rn(r0, r1);
    }
}

// ---------------- weight transpose + fp16: [K][N] -> [N][K] -------
__global__ void k_wsplit(const float* __restrict__ in, int K, int N, int which)
{
    __half* oh = which ? g_w2 : g_w1;
    __shared__ float t[32][33];
    int k0 = blockIdx.y*32, n0 = blockIdx.x*32;
    int x = threadIdx.x, y = threadIdx.y;
#pragma unroll
    for (int i = 0; i < 32; i += 8)
        t[y+i][x] = in[(size_t)(k0+y+i)*N + n0 + x];
    __syncthreads();
#pragma unroll
    for (int i = 0; i < 32; i += 8)
        oh[(size_t)(n0+y+i)*K + k0 + x] = __float2half_rn(t[x][y+i]);
}

// ---------------- HMMA fp16 GEMM (128x128 CTA, K-chunk 64) --------
#define STG   36864
#define NSTG  3
#define GEMM_SMEM (NSTG*STG)

__global__ __launch_bounds__(256, 2) void mma_gemm(const float* __restrict__ bias,
                                                   float* __restrict__ outp,
                                                   int K, int Nn, int epi)
{
    extern __shared__ char smem[];
    uint32_t sb = smem_u32(smem);

    const __half *Ah, *Bw;
    if (epi == 0) { Ah = g_cat; Bw = g_w1; }
    else          { Ah = g_hid; Bw = g_w2; }

    int tid = threadIdx.x, lane = tid & 31, wid = tid >> 5;
    int warpM = wid & 1, warpN = wid >> 1;
    int bm = blockIdx.y*128, bn = blockIdx.x*128;
    int nch = K >> 6;

    const __half* Abase = Ah + (size_t)bm*K;
    const __half* Bbase = Bw + (size_t)bn*K;

    float acc[4][4][4];
#pragma unroll
    for (int a = 0; a < 4; a++)
#pragma unroll
        for (int b = 0; b < 4; b++)
#pragma unroll
            for (int c = 0; c < 4; c++) acc[a][b][c] = 0.f;

#define LOAD_CHUNK(i) do { \
    int _k0 = (i) << 6; \
    uint32_t _st = sb + ((i) % NSTG) * STG; \
    _Pragma("unroll") \
    for (int _j = 0; _j < 4; _j++) { \
        int _u = tid + _j*256; \
        int _r = _u >> 3, _kb = _u & 7; \
        size_t _go = (size_t)_r*K + _k0 + _kb*8; \
        uint32_t _do_ = (uint32_t)(_r*144 + _kb*16); \
        CP16(_st + _do_,          Abase + _go); \
        CP16(_st + 18432 + _do_,  Bbase + _go); \
    } \
} while (0)

    LOAD_CHUNK(0); CP_COMMIT();
    if (nch > 1) LOAD_CHUNK(1);
    CP_COMMIT();

    int arow = warpM*64 + (lane & 7) + ((lane >> 3) & 1)*8;
    uint32_t akb = ((lane >> 4) & 1)*16;
    int brow = warpN*32 + ((lane >> 4) & 1)*8 + (lane & 7);
    uint32_t bkb = ((lane >> 3) & 1)*16;

    uint32_t a4[2][4][4], bfr[2][2][4];    // ks-parity double buffers

#define LD_FRAGS(st, kB, pb) do { \
    _Pragma("unroll") \
    for (int _mf = 0; _mf < 4; _mf++) \
        ldsm4(a4[pb][_mf], (st) + (uint32_t)(arow + _mf*16)*144 + akb + (kB)); \
    _Pragma("unroll") \
    for (int _np = 0; _np < 2; _np++) \
        ldsm4(bfr[pb][_np], (st) + 18432 + (uint32_t)(brow + _np*16)*144 + bkb + (kB)); \
} while (0)

    for (int i = 0; i < nch; i++) {
        CP_WAIT1();
        __syncthreads();
        if (i + 2 < nch) LOAD_CHUNK(i + 2);
        CP_COMMIT();

        uint32_t st = sb + (i % NSTG)*STG;
        LD_FRAGS(st, 0u, 0);
#pragma unroll
        for (int ks = 0; ks < 4; ks++) {
            int cur = ks & 1;
            if (ks < 3) LD_FRAGS(st, (uint32_t)(ks+1)*32, cur ^ 1);
#pragma unroll
            for (int mf = 0; mf < 4; mf++)
#pragma unroll
                for (int nf = 0; nf < 4; nf++) {
                    const uint32_t* bp = &bfr[cur][nf >> 1][(nf & 1)*2];
                    mma16816(acc[mf][nf], a4[cur][mf], bp);
                }
        }
    }
#undef LD_FRAGS

    // ---- epilogue (direct stores) ----
    int r0 = bm + warpM*64 + (lane >> 2);
    int cbase = bn + warpN*32 + (lane & 3)*2;
#pragma unroll
    for (int mf = 0; mf < 4; mf++) {
        int row0 = r0 + mf*16;
        int row1 = row0 + 8;
#pragma unroll
        for (int nf = 0; nf < 4; nf++) {
            int col = cbase + nf*8;
            float b0 = bias[col], b1 = bias[col + 1];
            float v00 = acc[mf][nf][0] + b0;
            float v01 = acc[mf][nf][1] + b1;
            float v10 = acc[mf][nf][2] + b0;
            float v11 = acc[mf][nf][3] + b1;
            if (epi == 0) {
                v00 = 0.5f*v00*(1.f + erff(v00*0.70710678118654752f));
                v01 = 0.5f*v01*(1.f + erff(v01*0.70710678118654752f));
                v10 = 0.5f*v10*(1.f + erff(v10*0.70710678118654752f));
                v11 = 0.5f*v11*(1.f + erff(v11*0.70710678118654752f));
                *(__half2*)(g_hid + (size_t)row0*HIDD + col) =
                    __half2(__float2half_rn(v00), __float2half_rn(v01));
                *(__half2*)(g_hid + (size_t)row1*HIDD + col) =
                    __half2(__float2half_rn(v10), __float2half_rn(v11));
            } else {
                int bb0 = row0 >> 14, n0 = row0 & 16383;
                int bb1 = row1 >> 14, n1 = row1 & 16383;
                size_t ob0 = (((size_t)bb0*2*Ntok) + Ntok + n0)*256;
                size_t ob1 = (((size_t)bb1*2*Ntok) + Ntok + n1)*256;
                *(float2*)(outp + ob0 + col) = make_float2(v00, v01);
                *(float2*)(outp + ob1 + col) = make_float2(v10, v11);
            }
        }
    }
}

// ---------------- launch (forked-stream graph, fully joined) -------
static cudaStream_t g_s1 = nullptr, g_s2 = nullptr;
static cudaEvent_t  g_e0 = nullptr, g_e1 = nullptr, g_e2 = nullptr,
                    g_e3 = nullptr, g_e5 = nullptr;

extern "C" void kernel_launch(void* const* d_in, const int* in_sizes, int n_in,
                              void* d_out, int out_size)
{
    (void)in_sizes; (void)n_in; (void)out_size;
    const float* x      = (const float*)d_in[0];
    const float* loc    = (const float*)d_in[1];
    const float* src    = (const float*)d_in[2];
    const float* w_delta = (const float*)d_in[7];
    const float* b_delta = (const float*)d_in[8];
    const float* n1g    = (const float*)d_in[9];
    const float* n1b    = (const float*)d_in[10];
    const float* conv_w = (const float*)d_in[11];
    const float* conv_b = (const float*)d_in[12];
    const float* n2g    = (const float*)d_in[13];
    const float* n2b    = (const float*)d_in[14];
    const float* fc1w   = (const float*)d_in[15];
    const float* fc1b   = (const float*)d_in[16];
    const float* fc2w   = (const float*)d_in[17];
    const float* fc2b   = (const float*)d_in[18];
    float* out = (float*)d_out;
    float* out_loc = out + (size_t)Bsz*2*Ntok*Dm;

    cudaFuncSetAttribute(mma_gemm, cudaFuncAttributeMaxDynamicSharedMemorySize, GEMM_SMEM);

    if (!g_s1) {
        cudaStreamCreateWithFlags(&g_s1, cudaStreamNonBlocking);
        cudaStreamCreateWithFlags(&g_s2, cudaStreamNonBlocking);
        cudaEventCreateWithFlags(&g_e0, cudaEventDisableTiming);
        cudaEventCreateWithFlags(&g_e1, cudaEventDisableTiming);
        cudaEventCreateWithFlags(&g_e2, cudaEventDisableTiming);
        cudaEventCreateWithFlags(&g_e3, cudaEventDisableTiming);
        cudaEventCreateWithFlags(&g_e5, cudaEventDisableTiming);
    }

    // fork
    cudaEventRecord(g_e0, 0);
    cudaStreamWaitEvent(g_s1, g_e0, 0);
    cudaStreamWaitEvent(g_s2, g_e0, 0);

    // branch s2: weight transpose + fp16 (needed by GEMMs only)
    k_wsplit<<<dim3(HIDD/32, CATD/32), dim3(32,8), 0, g_s2>>>(fc1w, CATD, HIDD, 0);
    k_wsplit<<<dim3(Dm/32,  HIDD/32), dim3(32,8), 0, g_s2>>>(fc2w, HIDD, Dm, 1);
    cudaEventRecord(g_e2, g_s2);

    // branch s1: scatter (g_acc pre-zeroed by PREVIOUS call / module init)
    k_scatter<<<Bsz*Ntok/8, 256, 0, g_s1>>>(x, loc);

    // main stream: delta (produces loc_extra), record for s1's gather
    k_delta<<<Bsz*Ntok/8, 256>>>(x, loc, w_delta, b_delta, n1g, n1b, out, out_loc);
    cudaEventRecord(g_e3, 0);

    // branch s1 continued: recon -> gather, then deferred re-zero (joined via e5)
    k_recon<<<Bsz*HWm/32, 256, 0, g_s1>>>();
    cudaStreamWaitEvent(g_s1, g_e3, 0);
    k_gather<<<Bsz*Ntok/8, 256, 0, g_s1>>>();
    cudaEventRecord(g_e1, g_s1);
    {
        size_t n4 = (size_t)Bsz*HWm*ACCW/4;
        k_zero_acc<<<(unsigned)((n4 + 255)/256), 256, 0, g_s1>>>();   // next call
    }
    cudaEventRecord(g_e5, g_s1);

    // main stream: patch (concurrent with recon/gather), then join
    k_patch<<<Bsz*Ntok/8, 512>>>(src, conv_w, conv_b, n2g, n2b);
    cudaStreamWaitEvent(0, g_e1, 0);       // cat fully ready
    cudaStreamWaitEvent(0, g_e2, 0);       // weights ready

    // MLP on tensor cores (fp16 single-term, fp32 accumulate), full-M launches
    mma_gemm<<<dim3(HIDD/128, Mrows/128), 256, GEMM_SMEM>>>(fc1b, nullptr, CATD, HIDD, 0);
    mma_gemm<<<dim3(Dm/128,   Mrows/128), 256, GEMM_SMEM>>>(fc2b, out,     HIDD, Dm,   1);

    // join s1 tail (deferred zero) into the capture-origin stream
    cudaStreamWaitEvent(0, g_e5, 0);
}